// round 6
// baseline (speedup 1.0000x reference)
#include <cuda_runtime.h>

#define BB   8
#define QQ   256
#define KK   1024
#define DD   256
#define HH   128
#define DVV  128
#define LOG2E 1.44269504088896340736f

// Scratch (allocation-free device globals). Ek4 padded by 2 h-quad rows so
// the software-pipeline tail prefetch never reads out of bounds.
__device__ float g_Eq [BB * QQ * HH];                    // [b][q][h]
__device__ float g_Ek4[BB * (HH/4) * KK * 4 + 2*KK*4];   // [b][h/4][k][4]

__device__ __forceinline__ float frcp(float x) {
    float r; asm("rcp.approx.f32 %0, %1;" : "=f"(r) : "f"(x)); return r;
}
__device__ __forceinline__ float fex2(float x) {
    float r; asm("ex2.approx.f32 %0, %1;" : "=f"(r) : "f"(x)); return r;
}

// ---------------------------------------------------------------------------
// Kernel 1: merged projection + exp. 16 rows/block, thread = column h.
// W in native [d][h] layout (coalesced), depth-2 prefetch, MOV-free.
// ---------------------------------------------------------------------------
#define PR 16
__global__ __launch_bounds__(128)
void proj_kernel(const float* __restrict__ Q, const float* __restrict__ Kx,
                 const float* __restrict__ Wq, const float* __restrict__ Wk) {
    __shared__ __align__(16) float xs[PR][DD];     // 16 input rows (16 KB)
    __shared__ float es[HH][PR + 1];               // padded transpose buffer
    int blk  = blockIdx.x;
    bool isK = blk >= (BB * QQ) / PR;              // >= 128
    int rowbase = isK ? (blk - (BB * QQ) / PR) * PR : blk * PR;
    const float* X = isK ? Kx : Q;
    const float* W = isK ? Wk : Wq;
    int tid = threadIdx.x;                          // 0..127 (= h)

    {   // coalesced float4 row load
        const float4* Xp = (const float4*)(X + (size_t)rowbase * DD);
        float4* xsp = (float4*)xs;
        for (int i = tid; i < PR * DD / 4; i += 128) xsp[i] = Xp[i];
    }
    __syncthreads();

    float acc[PR];
#pragma unroll
    for (int r = 0; r < PR; r++) acc[r] = 0.f;

    const float* Wp = W + tid;
    // alternating quad buffers (A used on even d4, B on odd), depth-2 pipeline
    float a0 = Wp[0*HH], a1 = Wp[1*HH], a2 = Wp[2*HH], a3 = Wp[3*HH];
    float b0 = Wp[4*HH], b1 = Wp[5*HH], b2 = Wp[6*HH], b3 = Wp[7*HH];

#define PROJ_BODY(c0, c1, c2, c3, dbase)                     \
    {                                                        \
        int d_ = (dbase);                                    \
        _Pragma("unroll")                                    \
        for (int r = 0; r < PR; r++) {                       \
            float4 x = *(const float4*)&xs[r][d_];           \
            acc[r] = fmaf(x.x, c0, acc[r]);                  \
            acc[r] = fmaf(x.y, c1, acc[r]);                  \
            acc[r] = fmaf(x.z, c2, acc[r]);                  \
            acc[r] = fmaf(x.w, c3, acc[r]);                  \
        }                                                    \
    }

    for (int d4 = 0; d4 < DD / 4; d4 += 2) {
        {   // even body: use A, refill A from d4+2 (clamped)
            PROJ_BODY(a0, a1, a2, a3, d4 * 4);
            const float* Wn = Wp + (size_t)((d4 + 2 < 64) ? (d4 + 2) : 63) * 4 * HH;
            a0 = Wn[0*HH]; a1 = Wn[1*HH]; a2 = Wn[2*HH]; a3 = Wn[3*HH];
        }
        {   // odd body: use B, refill B from d4+3 (clamped)
            PROJ_BODY(b0, b1, b2, b3, (d4 + 1) * 4);
            const float* Wn = Wp + (size_t)((d4 + 3 < 64) ? (d4 + 3) : 63) * 4 * HH;
            b0 = Wn[0*HH]; b1 = Wn[1*HH]; b2 = Wn[2*HH]; b3 = Wn[3*HH];
        }
    }
#undef PROJ_BODY

    if (!isK) {
#pragma unroll
        for (int r = 0; r < PR; r++)
            g_Eq[(rowbase + r) * HH + tid] = fex2(acc[r] * (2.0f * LOG2E));
    } else {
#pragma unroll
        for (int r = 0; r < PR; r++)
            es[tid][r] = fex2(acc[r] * (2.0f * LOG2E));
        __syncthreads();
        int b  = rowbase >> 10;
        int k0 = rowbase & 1023;
        for (int i = tid; i < HH * PR; i += 128) {
            int hq = i >> 6;              // 64 = PR*4 elements per h-quad
            int r  = (i >> 2) & (PR - 1);
            int h2 = i & 3;
            g_Ek4[(((size_t)b * (HH/4) + hq) * KK + k0 + r) * 4 + h2]
                = es[hq * 4 + h2][r];
        }
    }
}

// ---------------------------------------------------------------------------
// Kernel 2: fused scores + exp + denom + attn@V.
// Block = (b, tile of 4 q-rows), 512 blocks, 256 threads, 2 k per thread.
//   s(q,k) = sum_h (-2 w_h) * rcp(1 + Eq*Ek)   (wsum cancels in softmax)
// |s| small -> exp without max subtraction is fp32-safe.
// MOV-free depth-2 pipeline over interleaved Ek quads; one LDG.128 -> 16 elems.
// ---------------------------------------------------------------------------
#define ONEQ(c, e0q, e1q, e2q, e3q, wv, accq) do {                 \
    float E1_ = fmaf((c).x, (e0q), 1.f);                           \
    float E2_ = fmaf((c).y, (e1q), 1.f);                           \
    float num_ = fmaf((wv).x, E2_, (wv).y * E1_);                  \
    (accq) = fmaf(num_, frcp(E1_ * E2_), (accq));                  \
    float F1_ = fmaf((c).z, (e2q), 1.f);                           \
    float F2_ = fmaf((c).w, (e3q), 1.f);                           \
    float num2_ = fmaf((wv).z, F2_, (wv).w * F1_);                 \
    (accq) = fmaf(num2_, frcp(F1_ * F2_), (accq));                 \
} while (0)

#define BODY(ca, cb, hh, A0, A1) do {                              \
    float4 eq0_ = s_eq4[(hh)];                                     \
    float4 eq1_ = s_eq4[(hh) + 1];                                 \
    float4 eq2_ = s_eq4[(hh) + 2];                                 \
    float4 eq3_ = s_eq4[(hh) + 3];                                 \
    float4 w_ = *(const float4*)&s_w2[(hh)];                       \
    ONEQ(ca, eq0_.x, eq1_.x, eq2_.x, eq3_.x, w_, (A0).x);          \
    ONEQ(ca, eq0_.y, eq1_.y, eq2_.y, eq3_.y, w_, (A0).y);          \
    ONEQ(ca, eq0_.z, eq1_.z, eq2_.z, eq3_.z, w_, (A0).z);          \
    ONEQ(ca, eq0_.w, eq1_.w, eq2_.w, eq3_.w, w_, (A0).w);          \
    ONEQ(cb, eq0_.x, eq1_.x, eq2_.x, eq3_.x, w_, (A1).x);          \
    ONEQ(cb, eq0_.y, eq1_.y, eq2_.y, eq3_.y, w_, (A1).y);          \
    ONEQ(cb, eq0_.z, eq1_.z, eq2_.z, eq3_.z, w_, (A1).z);          \
    ONEQ(cb, eq0_.w, eq1_.w, eq2_.w, eq3_.w, w_, (A1).w);          \
} while (0)

__global__ __launch_bounds__(256, 4)
void attn_kernel(const float* __restrict__ values,
                 const int*   __restrict__ valid_lens,
                 const float* __restrict__ w_v,
                 float*       __restrict__ out) {
    __shared__ __align__(16) float4 s_eq4[HH];         // [h] -> q0..q3
    __shared__ __align__(16) float s_w2[HH];           // -2*w_v[h]
    __shared__ __align__(16) float s_scores[KK * 4];   // exp'ed probs [k][q]
    __shared__ __align__(16) float s_part[4][4][DVV];  // [kgroup][q][v]
    __shared__ float s_red[8][4];
    __shared__ float s_rden[4];

    int b  = blockIdx.x & 7;                // interleave batches across SMs
    int q0 = (blockIdx.x >> 3) * 4;
    int tid = threadIdx.x;
    int len = valid_lens[b];

    if (tid < HH) s_w2[tid] = -2.0f * w_v[tid];
    for (int i = tid; i < 4 * HH; i += 256) {
        int qq = i >> 7, h = i & 127;
        ((float*)&s_eq4[h])[qq] = g_Eq[((b * QQ) + q0 + qq) * HH + h];
    }
    __syncthreads();

    float4 sum = make_float4(0.f, 0.f, 0.f, 0.f);   // denom partials per q

    for (int kbase = 0; kbase < len; kbase += 512) {
        int k0 = kbase + tid * 2;
        if (k0 < len) {
            float4 a0 = make_float4(0.f, 0.f, 0.f, 0.f);  // k0,   q0..3
            float4 a1 = make_float4(0.f, 0.f, 0.f, 0.f);  // k0+1, q0..3
            const float4* pb = (const float4*)g_Ek4
                             + (size_t)b * (HH / 4) * KK + k0;
            float4 Aa = pb[0],  Ab = pb[1];       // hq
            float4 Ba = pb[KK], Bb = pb[KK + 1];  // hq+1
            const float4* pld = pb + 2 * KK;
#pragma unroll 2
            for (int hq = 0; hq < HH / 4; hq += 2) {
                int h = hq * 4;
                BODY(Aa, Ab, h, a0, a1);
                Aa = pld[0]; Ab = pld[1]; pld += KK;
                BODY(Ba, Bb, h + 4, a0, a1);
                Ba = pld[0]; Bb = pld[1]; pld += KK;
            }
            float4 eA, eB;
            eA.x = fex2(a0.x * LOG2E); eA.y = fex2(a0.y * LOG2E);
            eA.z = fex2(a0.z * LOG2E); eA.w = fex2(a0.w * LOG2E);
            eB.x = fex2(a1.x * LOG2E); eB.y = fex2(a1.y * LOG2E);
            eB.z = fex2(a1.z * LOG2E); eB.w = fex2(a1.w * LOG2E);
            *(float4*)&s_scores[k0 * 4]       = eA;
            *(float4*)&s_scores[(k0 + 1) * 4] = eB;
            sum.x += eA.x; sum.y += eA.y; sum.z += eA.z; sum.w += eA.w;
            if (k0 + 1 < len) {
                sum.x += eB.x; sum.y += eB.y; sum.z += eB.z; sum.w += eB.w;
            }
        }
    }

    // ---- denominator reduction ----
    int warp = tid >> 5, lane = tid & 31;
    for (int o = 16; o > 0; o >>= 1) {
        sum.x += __shfl_xor_sync(0xffffffffu, sum.x, o);
        sum.y += __shfl_xor_sync(0xffffffffu, sum.y, o);
        sum.z += __shfl_xor_sync(0xffffffffu, sum.z, o);
        sum.w += __shfl_xor_sync(0xffffffffu, sum.w, o);
    }
    if (lane == 0) {
        s_red[warp][0] = sum.x; s_red[warp][1] = sum.y;
        s_red[warp][2] = sum.z; s_red[warp][3] = sum.w;
    }
    __syncthreads();
    if (tid < 4) {
        float s = 0.f;
        for (int w = 0; w < 8; w++) s += s_red[w][tid];
        s_rden[tid] = frcp(s);
    }
    __syncthreads();

    // ---- attn @ V  (k in 4 strided groups; one LDS.128 feeds 8 FMAs) ----
    int g = tid >> 6;          // k-group
    int l = tid & 63;          // v pair index: v0 = 2*l
    float2 c0 = make_float2(0.f, 0.f), c1 = make_float2(0.f, 0.f);
    float2 c2 = make_float2(0.f, 0.f), c3 = make_float2(0.f, 0.f);
    const float2* Vp = (const float2*)(values + (size_t)b * KK * DVV) + l;
#pragma unroll 4
    for (int k = g; k < len; k += 4) {
        float4 p = *(const float4*)&s_scores[k * 4];
        float2 v = Vp[k * (DVV / 2)];
        c0.x = fmaf(p.x, v.x, c0.x); c0.y = fmaf(p.x, v.y, c0.y);
        c1.x = fmaf(p.y, v.x, c1.x); c1.y = fmaf(p.y, v.y, c1.y);
        c2.x = fmaf(p.z, v.x, c2.x); c2.y = fmaf(p.z, v.y, c2.y);
        c3.x = fmaf(p.w, v.x, c3.x); c3.y = fmaf(p.w, v.y, c3.y);
    }
    *(float2*)&s_part[g][0][2 * l] = c0;
    *(float2*)&s_part[g][1][2 * l] = c1;
    *(float2*)&s_part[g][2][2 * l] = c2;
    *(float2*)&s_part[g][3][2 * l] = c3;
    __syncthreads();

    // final combine: 512 outputs (4 q x 128 v), 2 per thread
#pragma unroll
    for (int j = 0; j < 2; j++) {
        int idx = tid + j * 256;
        int qq = idx >> 7;
        int v  = idx & 127;
        float rd = s_rden[qq];
        float o = s_part[0][qq][v] + s_part[1][qq][v]
                + s_part[2][qq][v] + s_part[3][qq][v];
        out[((size_t)(b * QQ + q0 + qq)) * DVV + v] = o * rd;
    }
}

extern "C" void kernel_launch(void* const* d_in, const int* in_sizes, int n_in,
                              void* d_out, int out_size) {
    const float* queries = (const float*)d_in[0];   // [8,256,256]
    const float* keys    = (const float*)d_in[1];   // [8,1024,256]
    const float* values  = (const float*)d_in[2];   // [8,1024,128]
    const int*   vlens   = (const int*)  d_in[3];   // [8]
    const float* W_q     = (const float*)d_in[4];   // [256,128]
    const float* W_k     = (const float*)d_in[5];   // [256,128]
    const float* w_v     = (const float*)d_in[6];   // [128]
    float* out = (float*)d_out;                     // [8,256,128]

    proj_kernel<<<(BB * QQ + BB * KK) / PR, 128>>>(queries, keys, W_q, W_k);
    attn_kernel<<<BB * (QQ / 4), 256>>>(values, vlens, w_v, out);
}